// round 2
// baseline (speedup 1.0000x reference)
#include <cuda_runtime.h>
#include <cstdint>

#define N_ROWS 8192
#define D_DIM 1024
#define K_CLS 80
#define KP1 81
#define M_CAND 2048
#define TOPK_N 100
#define IMG_H_F 800.0f
#define IMG_W_F 1216.0f
#define SCORE_T 0.05f
#define NMS_T 0.5f
#define SCALE_CLAMP_F 4.135166556742356f  // log(1000/16)

// ---------------- static device scratch (no allocs allowed) ----------------
__device__ uint64_t      g_keys[N_ROWS * K_CLS];      // 5.24 MB
__device__ unsigned int  g_hist[65536];
__device__ uint64_t      g_binbuf[8192];
__device__ uint64_t      g_selbuf[M_CAND];
__device__ int           g_B, g_countGt, g_needed;
__device__ unsigned int  g_nGt, g_nBin;
__device__ float         g_bboxWt[K_CLS * 4 * D_DIM]; // 1.31 MB, transposed bbox_w
__device__ float         g_candBoxes[M_CAND * 4];
__device__ int           g_selCls[M_CAND];
__device__ int           g_selProp[M_CAND];
__device__ float         g_selScore[M_CAND];
__device__ unsigned char g_selValid[M_CAND];
__device__ uint64_t      g_mask[M_CAND * 32];         // 512 KB

// ---------------- prep: zero hist + transpose bbox_w in one launch ----------------
__global__ void prep_kernel(const float* __restrict__ bw) {
    int i = blockIdx.x * blockDim.x + threadIdx.x;
    if (i < 320 * D_DIM) {
        int c = i / D_DIM, k = i % D_DIM;
        g_bboxWt[i] = bw[k * 320 + c];
    }
    if (i < 65536) g_hist[i] = 0;
    if (i == 0) { g_nGt = 0; g_nBin = 0; }
}

// ---------------- cls GEMM (8192x1024x81) + softmax + key build ----------------
__global__ __launch_bounds__(256, 2)
void gemm_cls_softmax(const float* __restrict__ x, const float* __restrict__ cw,
                      const float* __restrict__ cb) {
    __shared__ float xs[32][65];        // [k][row], padded
    __shared__ float ws[32][96];        // [k][col], cols padded 81->96 with 0
    __shared__ float logits[64][81];
    __shared__ float red[64][4];
    __shared__ float rmax[64], rsum[64];

    const int t = threadIdx.x;
    const int tx = t & 15, ty = t >> 4;
    const int row0 = blockIdx.x * 64;

    float acc[4][6];
#pragma unroll
    for (int i = 0; i < 4; i++)
#pragma unroll
        for (int j = 0; j < 6; j++) acc[i][j] = 0.f;

    for (int k0 = 0; k0 < D_DIM; k0 += 32) {
        for (int l = t; l < 64 * 32; l += 256) {
            int r = l >> 5, c = l & 31;
            xs[c][r] = x[(size_t)(row0 + r) * D_DIM + k0 + c];
        }
        for (int l = t; l < 32 * 96; l += 256) {
            int kk = l / 96, c = l - kk * 96;
            ws[kk][c] = (c < KP1) ? cw[(size_t)(k0 + kk) * KP1 + c] : 0.f;
        }
        __syncthreads();
#pragma unroll
        for (int kk = 0; kk < 32; kk++) {
            float xv[4], wv[6];
#pragma unroll
            for (int i = 0; i < 4; i++) xv[i] = xs[kk][ty + 16 * i];
#pragma unroll
            for (int j = 0; j < 6; j++) wv[j] = ws[kk][tx + 16 * j];
#pragma unroll
            for (int i = 0; i < 4; i++)
#pragma unroll
                for (int j = 0; j < 6; j++) acc[i][j] += xv[i] * wv[j];
        }
        __syncthreads();
    }
#pragma unroll
    for (int i = 0; i < 4; i++)
#pragma unroll
        for (int j = 0; j < 6; j++) {
            int c = tx + 16 * j;
            if (c < KP1) logits[ty + 16 * i][c] = acc[i][j] + cb[c];
        }
    __syncthreads();

    // softmax: 4 threads per row
    {
        int r = t & 63, p = t >> 6;
        float mx = -1e30f;
        for (int c = p; c < KP1; c += 4) mx = fmaxf(mx, logits[r][c]);
        red[r][p] = mx;
        __syncthreads();
        if (p == 0) rmax[r] = fmaxf(fmaxf(red[r][0], red[r][1]), fmaxf(red[r][2], red[r][3]));
        __syncthreads();
        float s = 0.f;
        float m = rmax[r];
        for (int c = p; c < KP1; c += 4) {
            float e = expf(logits[r][c] - m);
            logits[r][c] = e;
            s += e;
        }
        red[r][p] = s;
        __syncthreads();
        if (p == 0) rsum[r] = red[r][0] + red[r][1] + red[r][2] + red[r][3];
        __syncthreads();
    }
    // build keys for the first 80 cols (drop background), coalesced over c
    for (int l = t; l < 64 * K_CLS; l += 256) {
        int r = l / K_CLS, c = l - r * K_CLS;
        float pr = logits[r][c] / rsum[r];
        unsigned int bits = 0;
        if (pr > SCORE_T) {
            bits = __float_as_uint(pr);
            atomicAdd(&g_hist[bits >> 16], 1u);
        }
        int fid = (row0 + r) * K_CLS + c;
        g_keys[fid] = ((uint64_t)bits << 32) | (uint32_t)(~(uint32_t)fid);
    }
}

// ---------------- pick boundary bin: parallel suffix scan ----------------
__global__ __launch_bounds__(1024)
void pick_kernel2() {
    __shared__ unsigned sa[1024], sb[1024];
    __shared__ int sC;
    __shared__ unsigned fs[64];
    int t = threadIdx.x, w = t >> 5, l = t & 31;

    // coarse sums: warp w handles coarse bins w*32..w*32+31 (coalesced)
    for (int i = 0; i < 32; i++) {
        int c = w * 32 + i;
        unsigned v = g_hist[c * 64 + l] + g_hist[c * 64 + 32 + l];
#pragma unroll
        for (int o = 16; o; o >>= 1) v += __shfl_xor_sync(0xffffffffu, v, o);
        if (l == 0) sa[c] = v;
    }
    if (t == 0) sC = -1;
    __syncthreads();

    // suffix-sum (Hillis-Steele, ping-pong; 10 steps, ends in sa)
    unsigned* src = sa;
    unsigned* dst = sb;
    for (int d = 1; d < 1024; d <<= 1) {
        unsigned v = src[t] + ((t + d < 1024) ? src[t + d] : 0u);
        dst[t] = v;
        __syncthreads();
        unsigned* tmp = src; src = dst; dst = tmp;
    }
    unsigned suf_t = src[t];
    unsigned suf_n = (t < 1023) ? src[t + 1] : 0u;
    if (suf_t >= (unsigned)M_CAND && suf_n < (unsigned)M_CAND) sC = t;
    __syncthreads();
    int C = sC;
    if (C >= 0) {
        if (t < 64) fs[t] = g_hist[C * 64 + t];
        __syncthreads();
        if (t == 0) {
            unsigned cum = (C < 1023) ? src[C + 1] : 0u;
            int B = C * 64;
            unsigned cgt = cum;
            for (int b = 63; b >= 0; b--) {
                unsigned h = fs[b];
                if (cum + h >= (unsigned)M_CAND) { B = C * 64 + b; cgt = cum; break; }
                cum += h;
            }
            g_B = B;
            g_countGt = (int)cgt;
            g_needed = M_CAND - (int)cgt;
        }
    } else if (t == 0) {
        g_B = 0;
        g_countGt = (int)src[0];
        g_needed = M_CAND - (int)src[0];
    }
}

// ---------------- collect candidates above / at boundary bin ----------------
__global__ void collect_kernel() {
    int i = blockIdx.x * blockDim.x + threadIdx.x;
    if (i >= N_ROWS * K_CLS) return;
    uint64_t k = g_keys[i];
    int hi = (int)(k >> 48);
    int B = g_B;
    if (hi > B) {
        unsigned int p = atomicAdd(&g_nGt, 1u);
        g_selbuf[p] = k;
    } else if (hi == B) {
        unsigned int fid = ~(uint32_t)k;
        if (B != 0 || fid < 8192u) {
            unsigned int p = atomicAdd(&g_nBin, 1u);
            if (p < 8192u) g_binbuf[p] = k;
        }
    }
}

// ---------------- exact top-`need` from boundary bin via 8-bit radix descent ----------------
extern __shared__ uint64_t kbuf_dyn[];
__global__ __launch_bounds__(1024)
void binselect_kernel() {
    __shared__ unsigned hist[256];
    __shared__ unsigned long long prefix_sh;
    __shared__ unsigned r_sh, cnt_sh;
    int t = threadIdx.x;
    int need = g_needed;
    if (need <= 0) return;
    int n = min((int)g_nBin, 8192);

    for (int i = t; i < n; i += 1024) kbuf_dyn[i] = g_binbuf[i] & 0xFFFFFFFFFFFFull;
    if (t == 0) { prefix_sh = 0ull; r_sh = (unsigned)need; cnt_sh = 0; }
    __syncthreads();

    for (int lev = 5; lev >= 0; lev--) {
        int sh = lev * 8;
        for (int i = t; i < 256; i += 1024) hist[i] = 0;
        __syncthreads();
        unsigned long long pfx = prefix_sh;
        unsigned long long maskHi = (lev == 5) ? 0ull
            : ((0xFFFFFFFFFFFFull << (sh + 8)) & 0xFFFFFFFFFFFFull);
        for (int i = t; i < n; i += 1024) {
            unsigned long long k = kbuf_dyn[i];
            if (((k ^ pfx) & maskHi) == 0)
                atomicAdd(&hist[(unsigned)(k >> sh) & 255u], 1u);
        }
        __syncthreads();
        if (t == 0) {
            unsigned r = r_sh, cum = 0;
            int dd = 0;
            for (int d = 255; d >= 0; d--) {
                unsigned h = hist[d];
                if (cum + h >= r) { dd = d; break; }
                cum += h;
            }
            r_sh = r - cum;
            prefix_sh = pfx | ((unsigned long long)dd << sh);
        }
        __syncthreads();
    }
    unsigned long long T = prefix_sh;
    int base = g_countGt;
    for (int i = t; i < n; i += 1024) {
        if (kbuf_dyn[i] >= T) {
            unsigned p = atomicAdd(&cnt_sh, 1u);
            g_selbuf[base + p] = g_binbuf[i];
        }
    }
}

// ---------------- bitonic sort helper (descending, in shared) ----------------
__device__ __forceinline__ void bitonic_desc(uint64_t* sm, int n, int t, int nthr) {
    for (unsigned int size = 2; size <= (unsigned)n; size <<= 1) {
        for (unsigned int stride = size >> 1; stride > 0; stride >>= 1) {
            __syncthreads();
            for (unsigned int l = t; l < (unsigned)(n >> 1); l += nthr) {
                unsigned int i = 2u * l - (l & (stride - 1u));
                unsigned int j = i + stride;
                bool desc = (i & size) == 0;
                uint64_t a = sm[i], b = sm[j];
                if (desc ? (a < b) : (a > b)) { sm[i] = b; sm[j] = a; }
            }
        }
    }
    __syncthreads();
}

// ---------------- sort the 2048 selected, decode per-slot metadata ----------------
__global__ __launch_bounds__(1024)
void sortsel_kernel() {
    __shared__ uint64_t sm[M_CAND];
    int t = threadIdx.x;
    for (int i = t; i < M_CAND; i += 1024) sm[i] = g_selbuf[i];
    __syncthreads();
    bitonic_desc(sm, M_CAND, t, 1024);
    for (int s = t; s < M_CAND; s += 1024) {
        uint64_t k = sm[s];
        unsigned int bits = (unsigned int)(k >> 32);
        int fid = (int)(~(uint32_t)k);
        g_selScore[s] = bits ? __uint_as_float(bits) : -1.0f;
        g_selValid[s] = bits != 0;
        g_selCls[s] = fid % K_CLS;
        g_selProp[s] = fid / K_CLS;
    }
}

// ---------------- per-candidate bbox delta GEMV + decode + clip ----------------
__global__ __launch_bounds__(128)
void decode_kernel(const float* __restrict__ x, const float* __restrict__ bb,
                   const float* __restrict__ proposals) {
    int s = blockIdx.x;
    int cls = g_selCls[s], prop = g_selProp[s];
    int w = threadIdx.x >> 5, lane = threadIdx.x & 31;
    const float4* xr = (const float4*)(x + (size_t)prop * D_DIM);
    const float4* wr = (const float4*)(g_bboxWt + (size_t)(cls * 4 + w) * D_DIM);
    float acc = 0.f;
#pragma unroll
    for (int k = lane; k < D_DIM / 4; k += 32) {
        float4 xa = xr[k], wa = wr[k];
        acc += xa.x * wa.x + xa.y * wa.y + xa.z * wa.z + xa.w * wa.w;
    }
#pragma unroll
    for (int o = 16; o; o >>= 1) acc += __shfl_xor_sync(0xffffffffu, acc, o);
    __shared__ float d[4];
    if (lane == 0) d[w] = acc + bb[cls * 4 + w];
    __syncthreads();
    if (threadIdx.x == 0) {
        const float* pb = proposals + (size_t)prop * 4;
        float pw = pb[2] - pb[0], ph = pb[3] - pb[1];
        float cx = pb[0] + 0.5f * pw, cy = pb[1] + 0.5f * ph;
        float dx = d[0] / 10.0f, dy = d[1] / 10.0f;
        float dw = fminf(d[2] / 5.0f, SCALE_CLAMP_F);
        float dh = fminf(d[3] / 5.0f, SCALE_CLAMP_F);
        float pcx = dx * pw + cx, pcy = dy * ph + cy;
        float qw = expf(dw) * pw, qh = expf(dh) * ph;
        float x1 = pcx - 0.5f * qw, y1 = pcy - 0.5f * qh;
        float x2 = pcx + 0.5f * qw, y2 = pcy + 0.5f * qh;
        x1 = fminf(fmaxf(x1, 0.f), IMG_W_F);
        y1 = fminf(fmaxf(y1, 0.f), IMG_H_F);
        x2 = fminf(fmaxf(x2, 0.f), IMG_W_F);
        y2 = fminf(fmaxf(y2, 0.f), IMG_H_F);
        g_candBoxes[s * 4 + 0] = x1;
        g_candBoxes[s * 4 + 1] = y1;
        g_candBoxes[s * 4 + 2] = x2;
        g_candBoxes[s * 4 + 3] = y2;
    }
}

// ---------------- IoU suppression bitmask (class-aware) ----------------
__global__ __launch_bounds__(64)
void iou_kernel() {
    __shared__ float cb[64][4];
    __shared__ int ccls[64];
    int rb = blockIdx.y, cbk = blockIdx.x;
    int t = threadIdx.x;
    int j0 = cbk * 64;
    {
        int j = j0 + t;
        float4 b4 = ((const float4*)g_candBoxes)[j];
        cb[t][0] = b4.x; cb[t][1] = b4.y; cb[t][2] = b4.z; cb[t][3] = b4.w;
        ccls[t] = g_selCls[j];
    }
    __syncthreads();
    int i = rb * 64 + t;
    float4 bi = ((const float4*)g_candBoxes)[i];
    float bx1 = bi.x, by1 = bi.y, bx2 = bi.z, by2 = bi.w;
    float areaI = (bx2 - bx1) * (by2 - by1);
    int icls = g_selCls[i];
    uint64_t bits = 0;
#pragma unroll 4
    for (int jt = 0; jt < 64; jt++) {
        int jg = j0 + jt;
        if (jg > i && ccls[jt] == icls) {
            float ix1 = fmaxf(bx1, cb[jt][0]);
            float iy1 = fmaxf(by1, cb[jt][1]);
            float ix2 = fminf(bx2, cb[jt][2]);
            float iy2 = fminf(by2, cb[jt][3]);
            float inter = fmaxf(ix2 - ix1, 0.f) * fmaxf(iy2 - iy1, 0.f);
            float areaJ = (cb[jt][2] - cb[jt][0]) * (cb[jt][3] - cb[jt][1]);
            float uni = areaI + areaJ - inter;
            float iou = inter / fmaxf(uni, 1e-9f);
            if (iou > NMS_T) bits |= 1ull << jt;
        }
    }
    g_mask[(size_t)i * 32 + cbk] = bits;
}

// ---------------- serial NMS scan (grouped, short chain) + final top-100 ----------------
__global__ __launch_bounds__(128)
void nms_out_kernel(float* __restrict__ out, int out_size) {
    __shared__ unsigned long long keepm[32];
    __shared__ short fidx[TOPK_N];
    int t = threadIdx.x;

    if (t < 32) {
        int l = t;
        unsigned long long remv = 0;  // lane l owns suppression bits [l*64, l*64+64)
        for (int g = 0; g < 32; g++) {
            int r0 = g * 64 + l, r1 = g * 64 + 32 + l;
            unsigned long long mg0 = g_mask[(size_t)r0 * 32 + g];
            unsigned long long mg1 = g_mask[(size_t)r1 * 32 + g];
            unsigned v0 = g_selValid[r0], v1 = g_selValid[r1];
            unsigned vm0 = __ballot_sync(0xffffffffu, v0 != 0);
            unsigned vm1 = __ballot_sync(0xffffffffu, v1 != 0);
            unsigned long long vmask = (unsigned long long)vm0 |
                                       ((unsigned long long)vm1 << 32);
            unsigned long long cur = __shfl_sync(0xffffffffu, remv, g);
            unsigned long long acc = 0, kb = 0;
#pragma unroll
            for (int ii = 0; ii < 64; ii++) {
                unsigned long long mgi =
                    __shfl_sync(0xffffffffu, (ii < 32) ? mg0 : mg1, ii & 31);
                unsigned long long moi = g_mask[(size_t)(g * 64 + ii) * 32 + l];
                bool alive = ((vmask >> ii) & 1ull) && !((cur >> ii) & 1ull);
                if (alive) { cur |= mgi; acc |= moi; kb |= (1ull << ii); }
            }
            remv |= acc;
            if (l == 0) keepm[g] = kb;
        }
    }
    __syncthreads();
    if (t == 0) {
        int n = 0;
        for (int w = 0; w < 32 && n < TOPK_N; w++) {
            unsigned long long kb = keepm[w];
            while (kb && n < TOPK_N) {
                int b = __ffsll(kb) - 1;
                fidx[n++] = (short)(w * 64 + b);
                kb &= kb - 1;
            }
        }
        for (int w = 0; w < 32 && n < TOPK_N; w++) {
            unsigned long long nk = ~keepm[w];
            while (nk && n < TOPK_N) {
                int b = __ffsll(nk) - 1;
                fidx[n++] = (short)(w * 64 + b);
                nk &= nk - 1;
            }
        }
    }
    __syncthreads();
    for (int lq = t; lq < TOPK_N; lq += 128) {
        int s = fidx[lq];
        bool kp = (keepm[s >> 6] >> (s & 63)) & 1ull;
        if (4 * lq + 3 < out_size) {
            out[4 * lq + 0] = g_candBoxes[s * 4 + 0];
            out[4 * lq + 1] = g_candBoxes[s * 4 + 1];
            out[4 * lq + 2] = g_candBoxes[s * 4 + 2];
            out[4 * lq + 3] = g_candBoxes[s * 4 + 3];
        }
        if (400 + lq < out_size) out[400 + lq] = kp ? g_selScore[s] : -1.0f;
        if (500 + lq < out_size) out[500 + lq] = (float)g_selCls[s];
        if (600 + lq < out_size) out[600 + lq] = kp ? 1.0f : 0.0f;
    }
}

// ---------------- launcher ----------------
extern "C" void kernel_launch(void* const* d_in, const int* in_sizes, int n_in,
                              void* d_out, int out_size) {
    const float* x         = (const float*)d_in[0];
    const float* cls_w     = (const float*)d_in[1];
    const float* cls_b     = (const float*)d_in[2];
    const float* bbox_w    = (const float*)d_in[3];
    const float* bbox_b    = (const float*)d_in[4];
    const float* proposals = (const float*)d_in[5];
    float* out = (float*)d_out;

    cudaFuncSetAttribute(binselect_kernel, cudaFuncAttributeMaxDynamicSharedMemorySize, 65536);

    prep_kernel<<<1280, 256>>>(bbox_w);
    gemm_cls_softmax<<<N_ROWS / 64, 256>>>(x, cls_w, cls_b);
    pick_kernel2<<<1, 1024>>>();
    collect_kernel<<<(N_ROWS * K_CLS) / 256, 256>>>();
    binselect_kernel<<<1, 1024, 65536>>>();
    sortsel_kernel<<<1, 1024>>>();
    decode_kernel<<<M_CAND, 128>>>(x, bbox_b, proposals);
    iou_kernel<<<dim3(32, 32), 64>>>();
    nms_out_kernel<<<1, 128>>>(out, out_size);
}